// round 1
// baseline (speedup 1.0000x reference)
#include <cuda_runtime.h>
#include <cuda_bf16.h>
#include <cstdint>

// Problem constants
// input  [32, 64, 56, 56] fp32
// weight [128, 64, 3, 3]  fp32
// bias   [128]            fp32
// output [32, 128, 56, 56] fp32
// Implicit GEMM: M = 32*56*56 = 100352, N = 128, K = 64*9 = 576
// Decomposed: 9 outer (kh,kw) steps, each a K=64 (channels) GEMM chunk.

#define BATCH 32
#define CIN 64
#define HW 56
#define NOUT 128
#define PIX (HW*HW)            // 3136
#define MTOT (BATCH*PIX)       // 100352
#define BM 128
#define PADK 72                // smem k-stride (16B aligned, ldmatrix conflict-free)
#define PADE 132               // epilogue smem m-stride (floats)

// Pre-quantized weights: layout [kk=kh*3+kw][n][c], bf16
__device__ __align__(16) __nv_bfloat16 g_Wq[9 * NOUT * CIN];

__global__ void prep_weights(const float* __restrict__ w) {
    int idx = blockIdx.x * 256 + threadIdx.x;   // 9*128*64 = 73728
    if (idx < 9 * NOUT * CIN) {
        int c  = idx & 63;
        int n  = (idx >> 6) & 127;
        int kk = idx >> 13;
        // source weight[n][c][kh][kw] flat = (n*64+c)*9 + kk
        g_Wq[idx] = __float2bfloat16(w[(n * CIN + c) * 9 + kk]);
    }
}

__device__ __forceinline__ void ldmatrix_x4(uint32_t* r, uint32_t addr) {
    asm volatile("ldmatrix.sync.aligned.m8n8.x4.shared.b16 {%0,%1,%2,%3}, [%4];\n"
                 : "=r"(r[0]), "=r"(r[1]), "=r"(r[2]), "=r"(r[3]) : "r"(addr));
}
__device__ __forceinline__ void ldmatrix_x2(uint32_t* r, uint32_t addr) {
    asm volatile("ldmatrix.sync.aligned.m8n8.x2.shared.b16 {%0,%1}, [%2];\n"
                 : "=r"(r[0]), "=r"(r[1]) : "r"(addr));
}
__device__ __forceinline__ void mma_bf16(float* c, const uint32_t* a, const uint32_t* b) {
    asm volatile("mma.sync.aligned.m16n8k16.row.col.f32.bf16.bf16.f32 "
                 "{%0,%1,%2,%3}, {%4,%5,%6,%7}, {%8,%9}, {%0,%1,%2,%3};\n"
                 : "+f"(c[0]), "+f"(c[1]), "+f"(c[2]), "+f"(c[3])
                 : "r"(a[0]), "r"(a[1]), "r"(a[2]), "r"(a[3]),
                   "r"(b[0]), "r"(b[1]));
}

__global__ __launch_bounds__(256, 2)
void qconv_mma(const float* __restrict__ in,
               const float* __restrict__ bias,
               float* __restrict__ out) {
    // Shared: tile buffers (36864B) overlaid with epilogue buffer (33792B)
    __shared__ __align__(16) unsigned char smem_buf[2 * BM * PADK * 2];
    __shared__ float bias_s[NOUT];

    __nv_bfloat16* As = reinterpret_cast<__nv_bfloat16*>(smem_buf);
    __nv_bfloat16* Bs = As + BM * PADK;
    float* Ep = reinterpret_cast<float*>(smem_buf);

    const int tid  = threadIdx.x;
    const int lane = tid & 31;
    const int warp = tid >> 5;
    const int wm   = (warp & 1) * 64;       // warp M offset
    const int wn   = (warp >> 1) * 32;      // warp N offset

    if (tid < NOUT) bias_s[tid] = __bfloat162float(__float2bfloat16(bias[tid]));

    // per-thread pixel decode (m_l = tid & 127)
    const int m_l = tid & 127;
    const int c_half = tid >> 7;             // 0 or 1
    const int m = blockIdx.x * BM + m_l;
    const int b  = m / PIX;
    const int r  = m - b * PIX;
    const int oh = r / HW;
    const int ow = r - oh * HW;

    uint32_t asmem = (uint32_t)__cvta_generic_to_shared(As);
    uint32_t bsmem = (uint32_t)__cvta_generic_to_shared(Bs);

    float acc[4][4][4];
#pragma unroll
    for (int mi = 0; mi < 4; mi++)
#pragma unroll
        for (int ni = 0; ni < 4; ni++)
#pragma unroll
            for (int j = 0; j < 4; j++) acc[mi][ni][j] = 0.f;

#pragma unroll 1
    for (int kk = 0; kk < 9; kk++) {
        const int kh = kk / 3, kw = kk - kh * 3;
        const int ih = oh + kh - 1;
        const int iw = ow + kw - 1;
        const bool valid = ((unsigned)ih < HW) && ((unsigned)iw < HW);
        const float* src = in + (((b * CIN + c_half) * HW + ih) * HW + iw);

        // ---- A tile: 128 m x 64 c, fp32 -> bf16 quantize ----
#pragma unroll
        for (int i = 0; i < 32; i++) {
            int c = c_half + 2 * i;
            float v = valid ? src[(2 * i) * PIX] : 0.f;
            As[m_l * PADK + c] = __float2bfloat16(v);
        }
        // ---- B tile: copy pre-quantized weights [n][c] -> smem ----
        const uint4* wsrc = reinterpret_cast<const uint4*>(g_Wq + kk * (NOUT * CIN));
#pragma unroll
        for (int i = 0; i < 4; i++) {
            int idx = tid + i * 256;          // 0..1023 uint4
            int row = idx >> 3, col8 = idx & 7;
            *reinterpret_cast<uint4*>(&Bs[row * PADK + col8 * 8]) = wsrc[idx];
        }
        __syncthreads();

        // ---- 4 k-steps of 16 ----
#pragma unroll
        for (int ks = 0; ks < 4; ks++) {
            uint32_t af[4][4];
#pragma unroll
            for (int mi = 0; mi < 4; mi++) {
                uint32_t addr = asmem +
                    (((wm + mi * 16 + (lane & 15)) * PADK) + ks * 16 + (lane >> 4) * 8) * 2;
                ldmatrix_x4(af[mi], addr);
            }
            uint32_t bfr[4][2];
#pragma unroll
            for (int ni = 0; ni < 4; ni++) {
                uint32_t addr = bsmem +
                    (((wn + ni * 8 + (lane & 7)) * PADK) + ks * 16 + ((lane >> 3) & 1) * 8) * 2;
                ldmatrix_x2(bfr[ni], addr);
            }
#pragma unroll
            for (int mi = 0; mi < 4; mi++)
#pragma unroll
                for (int ni = 0; ni < 4; ni++)
                    mma_bf16(acc[mi][ni], af[mi], bfr[ni]);
        }
        __syncthreads();
    }

    // ---- Epilogue: two passes of 64 channels through smem transpose ----
    const long long obase = (long long)b * (NOUT * PIX) + r;
#pragma unroll 1
    for (int p = 0; p < 2; p++) {
        if ((wn >> 6) == p) {
#pragma unroll
            for (int mi = 0; mi < 4; mi++)
#pragma unroll
                for (int ni = 0; ni < 4; ni++) {
                    int ncol = (wn & 63) + ni * 8 + 2 * (lane & 3);
                    int mrow = wm + mi * 16 + (lane >> 2);
                    Ep[(ncol + 0) * PADE + mrow]     = acc[mi][ni][0];
                    Ep[(ncol + 1) * PADE + mrow]     = acc[mi][ni][1];
                    Ep[(ncol + 0) * PADE + mrow + 8] = acc[mi][ni][2];
                    Ep[(ncol + 1) * PADE + mrow + 8] = acc[mi][ni][3];
                }
        }
        __syncthreads();
#pragma unroll
        for (int i = 0; i < 32; i++) {
            int n_l = (tid >> 7) + 2 * i;     // 0..63
            float v = Ep[n_l * PADE + m_l] + bias_s[p * 64 + n_l];
            out[obase + (long long)(p * 64 + n_l) * PIX] = v;
        }
        __syncthreads();
    }
}

extern "C" void kernel_launch(void* const* d_in, const int* in_sizes, int n_in,
                              void* d_out, int out_size) {
    const float* inp    = (const float*)d_in[0];
    const float* weight = (const float*)d_in[1];
    const float* bias   = (const float*)d_in[2];
    float* out = (float*)d_out;
    (void)in_sizes; (void)n_in; (void)out_size;

    prep_weights<<<(9 * NOUT * CIN + 255) / 256, 256>>>(weight);
    qconv_mma<<<MTOT / BM, 256>>>(inp, bias, out);
}